// round 2
// baseline (speedup 1.0000x reference)
#include <cuda_runtime.h>
#include <cstdint>
#include <math.h>

#define NN   400000
#define NE   1600000
#define FIN  100
#define EMB  128
#define GG   11
#define SORTK 64
#define DCAT 385   // 3*EMB + 1
#define NBIG ((size_t)NN * EMB)

// ---------------- device scratch (static, no allocation) ----------------
__device__ float g_z1[51200000];   // pre-tanh layer-1 output
__device__ float g_z2[51200000];
__device__ float g_z3[51200000];
__device__ float g_h [51200000];   // h = act(x_prev) @ W  (current layer)
__device__ float g_z4[NN];
__device__ float g_h4[NN];
__device__ float g_deg[NN];
__device__ float g_dis[NN];
__device__ float g_norm[NE];
__device__ float g_sw[NN];         // working copy of score for top-k masking
__device__ int   g_topk[GG * SORTK];
__device__ float g_h5[GG * 64 * 64];
__device__ float g_h6[GG * 128 * 28];
__device__ float g_o128[128];

// ---------------- degree / norm ----------------
__global__ void k_deg_init(float* deg, int n) {
    int i = blockIdx.x * blockDim.x + threadIdx.x;
    if (i < n) deg[i] = 1.0f;
}
__global__ void k_deg_scatter(const int* __restrict__ src, const int* __restrict__ dst,
                              float* deg, int e) {
    int i = blockIdx.x * blockDim.x + threadIdx.x;
    if (i < e) {
        int s = src[i], d = dst[i];
        if (s != d) atomicAdd(&deg[d], 1.0f);
    }
}
__global__ void k_dis(const float* __restrict__ deg, float* dis, int n) {
    int i = blockIdx.x * blockDim.x + threadIdx.x;
    if (i < n) dis[i] = rsqrtf(deg[i]);
}
__global__ void k_norm(const int* __restrict__ src, const int* __restrict__ dst,
                       const float* __restrict__ dis, float* norm, int e) {
    int i = blockIdx.x * blockDim.x + threadIdx.x;
    if (i < e) {
        int s = src[i], d = dst[i];
        norm[i] = (s != d) ? dis[s] * dis[d] : 0.0f;
    }
}

// ---------------- GEMM: C = act(A) @ B ; also Z = C*dis^2 + bias ----------------
// A: M x K row-major, B: K x 128 row-major, C/Z: M x 128.
// BM=64, BN=128, BK=16, 256 threads, thread tile 4x8.
template<bool TANH_A>
__global__ __launch_bounds__(256)
void k_gemm(const float* __restrict__ A, const float* __restrict__ B,
            float* __restrict__ C, float* __restrict__ Z,
            const float* __restrict__ dis, const float* __restrict__ bias,
            int K) {
    __shared__ float As[16][64];
    __shared__ float Bs[16][128];

    const int tid = threadIdx.x;
    const int ty = tid >> 4;           // 0..15
    const int tx = tid & 15;           // 0..15
    const int m0 = ty * 4;             // row in tile
    const int n0 = tx * 8;             // col in tile
    const int blockRow = blockIdx.x;   // 6250 blocks, 64 rows each

    const int aRow  = tid >> 2;        // 0..63
    const int aCol4 = (tid & 3) * 4;   // 0,4,8,12
    const int bk    = tid >> 4;        // 0..15
    const int bn    = (tid & 15) * 8;  // 0..120

    float acc[4][8];
#pragma unroll
    for (int i = 0; i < 4; i++)
#pragma unroll
        for (int j = 0; j < 8; j++) acc[i][j] = 0.0f;

    const size_t gRow = (size_t)blockRow * 64 + aRow;

    for (int kt = 0; kt < K; kt += 16) {
        // load A tile (64 x 16), transposed into As[k][m]
        {
            int kk = kt + aCol4;
            if (kk + 3 < K) {
                float4 v = *reinterpret_cast<const float4*>(A + gRow * K + kk);
                float vv[4] = {v.x, v.y, v.z, v.w};
#pragma unroll
                for (int q = 0; q < 4; q++) {
                    float t = vv[q];
                    if (TANH_A) t = tanhf(t);
                    As[aCol4 + q][aRow] = t;
                }
            } else {
#pragma unroll
                for (int q = 0; q < 4; q++) {
                    int kq = kk + q;
                    float t = 0.0f;
                    if (kq < K) {
                        t = A[gRow * K + kq];
                        if (TANH_A) t = tanhf(t);
                    }
                    As[aCol4 + q][aRow] = t;
                }
            }
        }
        // load B tile (16 x 128)
        {
            int kq = kt + bk;
            if (kq < K) {
                float4 v0 = *reinterpret_cast<const float4*>(B + (size_t)kq * 128 + bn);
                float4 v1 = *reinterpret_cast<const float4*>(B + (size_t)kq * 128 + bn + 4);
                *reinterpret_cast<float4*>(&Bs[bk][bn])     = v0;
                *reinterpret_cast<float4*>(&Bs[bk][bn + 4]) = v1;
            } else {
                float4 z = {0, 0, 0, 0};
                *reinterpret_cast<float4*>(&Bs[bk][bn])     = z;
                *reinterpret_cast<float4*>(&Bs[bk][bn + 4]) = z;
            }
        }
        __syncthreads();

#pragma unroll
        for (int k = 0; k < 16; k++) {
            float4 a4 = *reinterpret_cast<const float4*>(&As[k][m0]);
            float4 b0 = *reinterpret_cast<const float4*>(&Bs[k][n0]);
            float4 b1 = *reinterpret_cast<const float4*>(&Bs[k][n0 + 4]);
            float a[4] = {a4.x, a4.y, a4.z, a4.w};
            float b[8] = {b0.x, b0.y, b0.z, b0.w, b1.x, b1.y, b1.z, b1.w};
#pragma unroll
            for (int i = 0; i < 4; i++)
#pragma unroll
                for (int j = 0; j < 8; j++)
                    acc[i][j] += a[i] * b[j];
        }
        __syncthreads();
    }

    float bcol[8];
#pragma unroll
    for (int j = 0; j < 8; j++) bcol[j] = bias[n0 + j];

#pragma unroll
    for (int i = 0; i < 4; i++) {
        size_t row = (size_t)blockRow * 64 + m0 + i;
        float sn = dis[row]; sn *= sn;
        size_t base = row * 128 + n0;
#pragma unroll
        for (int j = 0; j < 8; j++) {
            float hv = acc[i][j];
            C[base + j] = hv;
            Z[base + j] = hv * sn + bcol[j];
        }
    }
}

// ---------------- edge scatter: Z[dst] += h[src] * norm  (128 channels) ----------------
__global__ __launch_bounds__(256)
void k_scatter(const float* __restrict__ h, const int* __restrict__ src,
               const int* __restrict__ dst, const float* __restrict__ norm,
               float* Z, int e) {
    int warp = (blockIdx.x * blockDim.x + threadIdx.x) >> 5;
    if (warp >= e) return;
    int lane = threadIdx.x & 31;
    float w = norm[warp];
    if (w == 0.0f) return;
    int s = src[warp], d = dst[warp];
    float4 v = reinterpret_cast<const float4*>(h + (size_t)s * 128)[lane];
    float* zp = Z + (size_t)d * 128 + lane * 4;
    atomicAdd(zp + 0, v.x * w);
    atomicAdd(zp + 1, v.y * w);
    atomicAdd(zp + 2, v.z * w);
    atomicAdd(zp + 3, v.w * w);
}

// ---------------- layer 4 (1 channel): h4 = tanh(z3) @ W4; z4 = h4*sn + b4 ----------------
__global__ __launch_bounds__(256)
void k_gemv4(const float* __restrict__ z3, const float* __restrict__ W4,
             const float* __restrict__ b4, const float* __restrict__ dis,
             float* h4, float* z4, int n) {
    int warp = (blockIdx.x * blockDim.x + threadIdx.x) >> 5;
    if (warp >= n) return;
    int lane = threadIdx.x & 31;
    float4 v = reinterpret_cast<const float4*>(z3 + (size_t)warp * 128)[lane];
    float4 w = reinterpret_cast<const float4*>(W4)[lane];
    float acc = tanhf(v.x) * w.x + tanhf(v.y) * w.y + tanhf(v.z) * w.z + tanhf(v.w) * w.w;
#pragma unroll
    for (int o = 16; o > 0; o >>= 1) acc += __shfl_down_sync(0xffffffffu, acc, o);
    if (lane == 0) {
        float sn = dis[warp]; sn *= sn;
        h4[warp] = acc;
        z4[warp] = acc * sn + b4[0];
    }
}
__global__ void k_scatter1(const float* __restrict__ h4, const int* __restrict__ src,
                           const int* __restrict__ dst, const float* __restrict__ norm,
                           float* z4, int e) {
    int i = blockIdx.x * blockDim.x + threadIdx.x;
    if (i >= e) return;
    float w = norm[i];
    if (w == 0.0f) return;
    atomicAdd(&z4[dst[i]], h4[src[i]] * w);
}
__global__ void k_score(const float* __restrict__ z4, float* sw, int n) {
    int i = blockIdx.x * blockDim.x + threadIdx.x;
    if (i < n) sw[i] = tanhf(z4[i]);
}

// ---------------- top-64 per graph (lexsort-compatible) ----------------
__device__ __forceinline__ int lower_bound_i(const int* b, int n, int v) {
    int lo = 0, hi = n;
    while (lo < hi) { int m = (lo + hi) >> 1; if (b[m] < v) lo = m + 1; else hi = m; }
    return lo;
}
__global__ __launch_bounds__(1024)
void k_topk(const int* __restrict__ batch, float* sw, int* topk, int n) {
    int g = blockIdx.x;
    int start = lower_bound_i(batch, n, g);
    int end   = lower_bound_i(batch, n, g + 1);
    __shared__ unsigned long long sk[1024];
    for (int r = 0; r < SORTK; r++) {
        unsigned long long best = 0ULL;
        for (int i = start + threadIdx.x; i < end; i += blockDim.x) {
            float s = sw[i];
            unsigned u = __float_as_uint(s);
            u = (u & 0x80000000u) ? ~u : (u | 0x80000000u);
            unsigned long long key = ((unsigned long long)u << 32) | (unsigned)(~i);
            if (key > best) best = key;
        }
        sk[threadIdx.x] = best;
        __syncthreads();
        for (int s = 512; s > 0; s >>= 1) {
            if (threadIdx.x < s) {
                unsigned long long o = sk[threadIdx.x + s];
                if (o > sk[threadIdx.x]) sk[threadIdx.x] = o;
            }
            __syncthreads();
        }
        if (threadIdx.x == 0) {
            unsigned long long b = sk[0];
            unsigned up = (unsigned)(b >> 32);
            if (b == 0ULL || up == 0x007FFFFFu) {   // empty or -inf (masked)
                topk[g * SORTK + r] = -1;
            } else {
                int idx = (int)(~(unsigned)(b & 0xffffffffu));
                topk[g * SORTK + r] = idx;
                sw[idx] = -INFINITY;
            }
        }
        __syncthreads();
    }
}

// ---------------- conv5: per (graph, rank) 385-dot into 64 channels ----------------
__global__ __launch_bounds__(128)
void k_conv5(const int* __restrict__ topk,
             const float* __restrict__ z1, const float* __restrict__ z2,
             const float* __restrict__ z3, const float* __restrict__ z4,
             const float* __restrict__ cw5, const float* __restrict__ cb5,
             float* __restrict__ h5) {
    int g = blockIdx.x >> 6;
    int t = blockIdx.x & 63;
    int tid = threadIdx.x;
    __shared__ float feat[DCAT];
    int node = topk[g * SORTK + t];
    if (node >= 0) {
        size_t base = (size_t)node * 128;
        feat[tid]       = tanhf(z1[base + tid]);
        feat[128 + tid] = tanhf(z2[base + tid]);
        feat[256 + tid] = tanhf(z3[base + tid]);
        if (tid == 0) feat[384] = tanhf(z4[node]);
    } else {
        feat[tid] = 0.f; feat[128 + tid] = 0.f; feat[256 + tid] = 0.f;
        if (tid == 0) feat[384] = 0.f;
    }
    __syncthreads();
    if (tid < 64) {
        float acc = cb5[tid];
        const float* w = cw5 + (size_t)tid * DCAT;
        for (int k = 0; k < DCAT; k++) acc += w[k] * feat[k];
        h5[((size_t)g * 64 + tid) * 64 + t] = fmaxf(acc, 0.0f);
    }
}

// ---------------- maxpool(2) + conv6 (64ch -> 128ch, k=5) ----------------
__global__ __launch_bounds__(256)
void k_pool_conv6(const float* __restrict__ h5, const float* __restrict__ cw6,
                  const float* __restrict__ cb6, float* __restrict__ h6) {
    int g = blockIdx.x;
    __shared__ float hp[64][33];
    for (int idx = threadIdx.x; idx < 64 * 32; idx += blockDim.x) {
        int i = idx >> 5, u = idx & 31;
        float a = h5[((size_t)g * 64 + i) * 64 + 2 * u];
        float b = h5[((size_t)g * 64 + i) * 64 + 2 * u + 1];
        hp[i][u] = fmaxf(a, b);
    }
    __syncthreads();
    for (int idx = threadIdx.x; idx < 128 * 28; idx += blockDim.x) {
        int o = idx / 28, t = idx % 28;
        float acc = cb6[o];
        const float* w = cw6 + (size_t)o * 320;
#pragma unroll
        for (int i = 0; i < 64; i++) {
#pragma unroll
            for (int j = 0; j < 5; j++) acc += w[i * 5 + j] * hp[i][t + j];
        }
        h6[((size_t)g * 128 + o) * 28 + t] = fmaxf(acc, 0.0f);
    }
}

// ---------------- dense layers ----------------
__global__ __launch_bounds__(256)
void k_dense1(const float* __restrict__ h6, const float* __restrict__ fw1,
              const float* __restrict__ fb1, float* __restrict__ o128) {
    int m = blockIdx.x;
    const int E1 = GG * 128 * 28;  // 39424
    float acc = 0.f;
    const float* w = fw1 + (size_t)m * E1;
    for (int e = threadIdx.x; e < E1; e += 256) acc += h6[e] * w[e];
    __shared__ float s[256];
    s[threadIdx.x] = acc;
    __syncthreads();
    for (int t = 128; t > 0; t >>= 1) {
        if (threadIdx.x < t) s[threadIdx.x] += s[threadIdx.x + t];
        __syncthreads();
    }
    if (threadIdx.x == 0) o128[m] = fmaxf(s[0] + fb1[m], 0.0f);
}
__global__ void k_dense2(const float* __restrict__ o128, const float* __restrict__ fw2,
                         const float* __restrict__ fb2, float* __restrict__ out) {
    int j = threadIdx.x >> 5;
    int lane = threadIdx.x & 31;
    if (j < 10) {
        float acc = 0.f;
        for (int m = lane; m < 128; m += 32) acc += o128[m] * fw2[j * 128 + m];
#pragma unroll
        for (int o = 16; o > 0; o >>= 1) acc += __shfl_down_sync(0xffffffffu, acc, o);
        if (lane == 0) out[j] = acc + fb2[j];
    }
}

// ---------------- launch ----------------
extern "C" void kernel_launch(void* const* d_in, const int* in_sizes, int n_in,
                              void* d_out, int out_size) {
    const float* x   = (const float*)d_in[0];
    const int*   ei  = (const int*)  d_in[1];
    const int*   bat = (const int*)  d_in[2];
    const float* W1  = (const float*)d_in[3];
    const float* b1  = (const float*)d_in[4];
    const float* W2  = (const float*)d_in[5];
    const float* b2  = (const float*)d_in[6];
    const float* W3  = (const float*)d_in[7];
    const float* b3  = (const float*)d_in[8];
    const float* W4  = (const float*)d_in[9];
    const float* b4  = (const float*)d_in[10];
    const float* cw5 = (const float*)d_in[11];
    const float* cb5 = (const float*)d_in[12];
    const float* cw6 = (const float*)d_in[13];
    const float* cb6 = (const float*)d_in[14];
    const float* fw1 = (const float*)d_in[15];
    const float* fb1 = (const float*)d_in[16];
    const float* fw2 = (const float*)d_in[17];
    const float* fb2 = (const float*)d_in[18];

    const int* src = ei;
    const int* dst = ei + NE;

    float *z1, *z2, *z3, *h, *z4, *h4, *deg, *dis, *nrm, *sw, *h5, *h6, *o128;
    int* tk;
    cudaGetSymbolAddress((void**)&z1, g_z1);
    cudaGetSymbolAddress((void**)&z2, g_z2);
    cudaGetSymbolAddress((void**)&z3, g_z3);
    cudaGetSymbolAddress((void**)&h,  g_h);
    cudaGetSymbolAddress((void**)&z4, g_z4);
    cudaGetSymbolAddress((void**)&h4, g_h4);
    cudaGetSymbolAddress((void**)&deg, g_deg);
    cudaGetSymbolAddress((void**)&dis, g_dis);
    cudaGetSymbolAddress((void**)&nrm, g_norm);
    cudaGetSymbolAddress((void**)&sw, g_sw);
    cudaGetSymbolAddress((void**)&tk, g_topk);
    cudaGetSymbolAddress((void**)&h5, g_h5);
    cudaGetSymbolAddress((void**)&h6, g_h6);
    cudaGetSymbolAddress((void**)&o128, g_o128);

    const int TB = 256;
    // degrees and norms
    k_deg_init<<<(NN + TB - 1) / TB, TB>>>(deg, NN);
    k_deg_scatter<<<(NE + TB - 1) / TB, TB>>>(src, dst, deg, NE);
    k_dis<<<(NN + TB - 1) / TB, TB>>>(deg, dis, NN);
    k_norm<<<(NE + TB - 1) / TB, TB>>>(src, dst, dis, nrm, NE);

    const int GEMM_GRID = NN / 64;                  // 6250
    const int SCAT_GRID = (NE * 32) / TB;           // 200000

    // layer 1: A = x (no tanh), K=100
    k_gemm<false><<<GEMM_GRID, TB>>>(x, W1, h, z1, dis, b1, FIN);
    k_scatter<<<SCAT_GRID, TB>>>(h, src, dst, nrm, z1, NE);
    // layer 2
    k_gemm<true><<<GEMM_GRID, TB>>>(z1, W2, h, z2, dis, b2, EMB);
    k_scatter<<<SCAT_GRID, TB>>>(h, src, dst, nrm, z2, NE);
    // layer 3
    k_gemm<true><<<GEMM_GRID, TB>>>(z2, W3, h, z3, dis, b3, EMB);
    k_scatter<<<SCAT_GRID, TB>>>(h, src, dst, nrm, z3, NE);
    // layer 4 (single channel)
    k_gemv4<<<(NN * 32 + TB - 1) / TB, TB>>>(z3, W4, b4, dis, h4, z4, NN);
    k_scatter1<<<(NE + TB - 1) / TB, TB>>>(h4, src, dst, nrm, z4, NE);
    k_score<<<(NN + TB - 1) / TB, TB>>>(z4, sw, NN);

    // top-64 per graph
    k_topk<<<GG, 1024>>>(bat, sw, tk, NN);

    // readout
    k_conv5<<<GG * 64, 128>>>(tk, z1, z2, z3, z4, cw5, cb5, h5);
    k_pool_conv6<<<GG, 256>>>(h5, cw6, cb6, h6);
    k_dense1<<<128, 256>>>(h6, fw1, fb1, o128);
    k_dense2<<<1, 320>>>(o128, fw2, fb2, (float*)d_out);
}

// round 3
// speedup vs baseline: 1.5223x; 1.5223x over previous
#include <cuda_runtime.h>
#include <cstdint>
#include <math.h>

#define NN   400000
#define NE   1600000
#define FIN  100
#define EMB  128
#define GG   11
#define SORTK 64
#define DCAT 385   // 3*EMB + 1
#define TOPK_CAP 49152   // floats of dynamic smem cache (192 KB)

// ---------------- device scratch (static, no allocation) ----------------
__device__ float g_z1[51200000];   // pre-tanh layer-1 output
__device__ float g_z2[51200000];
__device__ float g_z3[51200000];
__device__ float g_h [51200000];   // h = act(x_prev) @ W  (current layer)
__device__ float g_z4[NN];
__device__ float g_h4[NN];
__device__ float g_deg[NN];
__device__ float g_dis[NN];
__device__ float g_norm[NE];
__device__ int   g_topk[GG * SORTK];
__device__ float g_h5[GG * 64 * 64];
__device__ float g_h6[GG * 128 * 28];
__device__ float g_o128[128];

// ---------------- degree / norm ----------------
__global__ void k_deg_init(float* deg, int n) {
    int i = blockIdx.x * blockDim.x + threadIdx.x;
    if (i < n) deg[i] = 1.0f;
}
__global__ void k_deg_scatter(const int* __restrict__ src, const int* __restrict__ dst,
                              float* deg, int e) {
    int i = blockIdx.x * blockDim.x + threadIdx.x;
    if (i < e) {
        int s = src[i], d = dst[i];
        if (s != d) atomicAdd(&deg[d], 1.0f);
    }
}
__global__ void k_dis(const float* __restrict__ deg, float* dis, int n) {
    int i = blockIdx.x * blockDim.x + threadIdx.x;
    if (i < n) dis[i] = rsqrtf(deg[i]);
}
__global__ void k_norm(const int* __restrict__ src, const int* __restrict__ dst,
                       const float* __restrict__ dis, float* norm, int e) {
    int i = blockIdx.x * blockDim.x + threadIdx.x;
    if (i < e) {
        int s = src[i], d = dst[i];
        norm[i] = (s != d) ? dis[s] * dis[d] : 0.0f;
    }
}

// ---------------- GEMM: C = act(A) @ B ; Z = C*dis^2 + bias ----------------
// A: M x K row-major, B: K x 128 row-major, C/Z: M x 128.
// BM=128, BN=128, BK=8, 256 threads, 8x8 microtile, double-buffered smem.
template<bool TANH_A>
__global__ __launch_bounds__(256, 2)
void k_gemm(const float* __restrict__ A, const float* __restrict__ B,
            float* __restrict__ C, float* __restrict__ Z,
            const float* __restrict__ dis, const float* __restrict__ bias,
            int K) {
    __shared__ float As[2][8][132];   // padded to avoid store bank conflicts
    __shared__ float Bs[2][8][128];

    const int tid = threadIdx.x;
    const int m0 = (tid >> 4) * 8;     // 0..120
    const int n0 = (tid & 15) * 8;     // 0..120
    const size_t rowBase = (size_t)blockIdx.x * 128;

    const int aRow = tid >> 1;         // 0..127
    const int aCg  = (tid & 1) * 4;    // 0 or 4
    const int bRow = tid >> 5;         // 0..7
    const int bCol = (tid & 31) * 4;   // 0..124

    const float* Aptr = A + (rowBase + aRow) * (size_t)K;
    const int tiles = (K + 7) / 8;

    float acc[8][8];
#pragma unroll
    for (int i = 0; i < 8; i++)
#pragma unroll
        for (int j = 0; j < 8; j++) acc[i][j] = 0.0f;

    float4 ra, rb;

    // ---- load tile t into registers ----
#define LOAD_T(t, RA, RB) do {                                              \
        int kk = (t) * 8 + aCg;                                             \
        if (kk + 3 < K) {                                                   \
            RA = *reinterpret_cast<const float4*>(Aptr + kk);               \
        } else {                                                            \
            float v0 = (kk + 0 < K) ? Aptr[kk + 0] : 0.0f;                  \
            float v1 = (kk + 1 < K) ? Aptr[kk + 1] : 0.0f;                  \
            float v2 = (kk + 2 < K) ? Aptr[kk + 2] : 0.0f;                  \
            float v3 = (kk + 3 < K) ? Aptr[kk + 3] : 0.0f;                  \
            RA = make_float4(v0, v1, v2, v3);                               \
        }                                                                   \
        int kq = (t) * 8 + bRow;                                            \
        if (kq < K) RB = *reinterpret_cast<const float4*>(B + (size_t)kq * 128 + bCol); \
        else        RB = make_float4(0.f, 0.f, 0.f, 0.f);                   \
    } while (0)

#define STORE_T(buf, RA, RB) do {                                           \
        float v0 = RA.x, v1 = RA.y, v2 = RA.z, v3 = RA.w;                   \
        if (TANH_A) { v0 = tanhf(v0); v1 = tanhf(v1); v2 = tanhf(v2); v3 = tanhf(v3); } \
        As[buf][aCg + 0][aRow] = v0;                                        \
        As[buf][aCg + 1][aRow] = v1;                                        \
        As[buf][aCg + 2][aRow] = v2;                                        \
        As[buf][aCg + 3][aRow] = v3;                                        \
        *reinterpret_cast<float4*>(&Bs[buf][bRow][bCol]) = RB;              \
    } while (0)

    LOAD_T(0, ra, rb);
    STORE_T(0, ra, rb);
    __syncthreads();

    for (int t = 0; t < tiles; t++) {
        const int cur = t & 1;
        const bool more = (t + 1 < tiles);
        float4 na, nb;
        if (more) LOAD_T(t + 1, na, nb);

#pragma unroll
        for (int k = 0; k < 8; k++) {
            float4 a0 = *reinterpret_cast<const float4*>(&As[cur][k][m0]);
            float4 a1 = *reinterpret_cast<const float4*>(&As[cur][k][m0 + 4]);
            float4 b0 = *reinterpret_cast<const float4*>(&Bs[cur][k][n0]);
            float4 b1 = *reinterpret_cast<const float4*>(&Bs[cur][k][n0 + 4]);
            float a[8] = {a0.x, a0.y, a0.z, a0.w, a1.x, a1.y, a1.z, a1.w};
            float b[8] = {b0.x, b0.y, b0.z, b0.w, b1.x, b1.y, b1.z, b1.w};
#pragma unroll
            for (int i = 0; i < 8; i++)
#pragma unroll
                for (int j = 0; j < 8; j++)
                    acc[i][j] += a[i] * b[j];
        }

        if (more) {
            STORE_T(cur ^ 1, na, nb);
            __syncthreads();
        }
    }
#undef LOAD_T
#undef STORE_T

    float bcol[8];
#pragma unroll
    for (int j = 0; j < 8; j++) bcol[j] = bias[n0 + j];

#pragma unroll
    for (int i = 0; i < 8; i++) {
        size_t row = rowBase + m0 + i;
        float sn = dis[row]; sn *= sn;
        size_t base = row * 128 + n0;
        float4 c0 = make_float4(acc[i][0], acc[i][1], acc[i][2], acc[i][3]);
        float4 c1 = make_float4(acc[i][4], acc[i][5], acc[i][6], acc[i][7]);
        *reinterpret_cast<float4*>(C + base)     = c0;
        *reinterpret_cast<float4*>(C + base + 4) = c1;
        float4 z0 = make_float4(c0.x * sn + bcol[0], c0.y * sn + bcol[1],
                                c0.z * sn + bcol[2], c0.w * sn + bcol[3]);
        float4 z1 = make_float4(c1.x * sn + bcol[4], c1.y * sn + bcol[5],
                                c1.z * sn + bcol[6], c1.w * sn + bcol[7]);
        *reinterpret_cast<float4*>(Z + base)     = z0;
        *reinterpret_cast<float4*>(Z + base + 4) = z1;
    }
}

// ---------------- edge scatter: Z[dst] += h[src] * norm (128 ch, vector RED) ----------------
__global__ __launch_bounds__(256)
void k_scatter(const float* __restrict__ h, const int* __restrict__ src,
               const int* __restrict__ dst, const float* __restrict__ norm,
               float* Z, int e) {
    int eid = (blockIdx.x * blockDim.x + threadIdx.x) >> 5;
    if (eid >= e) return;
    int lane = threadIdx.x & 31;
    float w = norm[eid];
    if (w == 0.0f) return;
    int s = src[eid], d = dst[eid];
    float4 v = __ldg(reinterpret_cast<const float4*>(h + (size_t)s * 128) + lane);
    float* zp = Z + (size_t)d * 128 + lane * 4;
    asm volatile("red.global.add.v4.f32 [%0], {%1, %2, %3, %4};"
                 :: "l"(zp), "f"(v.x * w), "f"(v.y * w), "f"(v.z * w), "f"(v.w * w)
                 : "memory");
}

// ---------------- layer 4 (1 channel) ----------------
__global__ __launch_bounds__(256)
void k_gemv4(const float* __restrict__ z3, const float* __restrict__ W4,
             const float* __restrict__ b4, const float* __restrict__ dis,
             float* h4, float* z4, int n) {
    int warp = (blockIdx.x * blockDim.x + threadIdx.x) >> 5;
    if (warp >= n) return;
    int lane = threadIdx.x & 31;
    float4 v = reinterpret_cast<const float4*>(z3 + (size_t)warp * 128)[lane];
    float4 w = reinterpret_cast<const float4*>(W4)[lane];
    float acc = tanhf(v.x) * w.x + tanhf(v.y) * w.y + tanhf(v.z) * w.z + tanhf(v.w) * w.w;
#pragma unroll
    for (int o = 16; o > 0; o >>= 1) acc += __shfl_down_sync(0xffffffffu, acc, o);
    if (lane == 0) {
        float sn = dis[warp]; sn *= sn;
        h4[warp] = acc;
        z4[warp] = acc * sn + b4[0];
    }
}
__global__ void k_scatter1(const float* __restrict__ h4, const int* __restrict__ src,
                           const int* __restrict__ dst, const float* __restrict__ norm,
                           float* z4, int e) {
    int i = blockIdx.x * blockDim.x + threadIdx.x;
    if (i >= e) return;
    float w = norm[i];
    if (w == 0.0f) return;
    atomicAdd(&z4[dst[i]], h4[src[i]] * w);
}

// ---------------- top-64 per graph (lexsort-compatible, smem-cached) ----------------
// tanh is monotonic -> rank directly on z4. Strictly-decreasing-key selection:
// round r picks max key among keys < prev round's key (keys unique via index bits).
__device__ __forceinline__ int lower_bound_i(const int* b, int n, int v) {
    int lo = 0, hi = n;
    while (lo < hi) { int m = (lo + hi) >> 1; if (b[m] < v) lo = m + 1; else hi = m; }
    return lo;
}
__global__ __launch_bounds__(512)
void k_topk(const int* __restrict__ batch, const float* __restrict__ z4,
            int* __restrict__ topk, int n) {
    int g = blockIdx.x;
    int start = lower_bound_i(batch, n, g);
    int end   = lower_bound_i(batch, n, g + 1);
    int len   = end - start;
    extern __shared__ float sc[];
    const bool cached = (len <= TOPK_CAP);
    if (cached) {
        for (int j = threadIdx.x; j < len; j += blockDim.x) sc[j] = z4[start + j];
    }
    __syncthreads();

    __shared__ unsigned long long warpmax[16];
    __shared__ unsigned long long bestsh;
    const int wid = threadIdx.x >> 5;
    const int lane = threadIdx.x & 31;
    unsigned long long prev = 0xFFFFFFFFFFFFFFFFULL;

    for (int r = 0; r < SORTK; r++) {
        unsigned long long best = 0ULL;
        for (int j = threadIdx.x; j < len; j += blockDim.x) {
            float s = cached ? sc[j] : z4[start + j];
            unsigned u = __float_as_uint(s);
            u = (u & 0x80000000u) ? ~u : (u | 0x80000000u);
            unsigned long long key = ((unsigned long long)u << 32)
                                   | (unsigned)(~(start + j));
            if (key < prev && key > best) best = key;
        }
#pragma unroll
        for (int o = 16; o > 0; o >>= 1) {
            unsigned long long t = __shfl_xor_sync(0xffffffffu, best, o);
            if (t > best) best = t;
        }
        if (lane == 0) warpmax[wid] = best;
        __syncthreads();
        if (wid == 0) {
            unsigned long long v = (lane < 16) ? warpmax[lane] : 0ULL;
#pragma unroll
            for (int o = 8; o > 0; o >>= 1) {
                unsigned long long t = __shfl_xor_sync(0xffffffffu, v, o);
                if (t > v) v = t;
            }
            if (lane == 0) {
                bestsh = v;
                topk[g * SORTK + r] = (v == 0ULL) ? -1
                                     : (int)(~(unsigned)(v & 0xffffffffu));
            }
        }
        __syncthreads();
        prev = bestsh;
        __syncthreads();
    }
}

// ---------------- conv5 ----------------
__global__ __launch_bounds__(128)
void k_conv5(const int* __restrict__ topk,
             const float* __restrict__ z1, const float* __restrict__ z2,
             const float* __restrict__ z3, const float* __restrict__ z4,
             const float* __restrict__ cw5, const float* __restrict__ cb5,
             float* __restrict__ h5) {
    int g = blockIdx.x >> 6;
    int t = blockIdx.x & 63;
    int tid = threadIdx.x;
    __shared__ float feat[DCAT];
    int node = topk[g * SORTK + t];
    if (node >= 0) {
        size_t base = (size_t)node * 128;
        feat[tid]       = tanhf(z1[base + tid]);
        feat[128 + tid] = tanhf(z2[base + tid]);
        feat[256 + tid] = tanhf(z3[base + tid]);
        if (tid == 0) feat[384] = tanhf(z4[node]);
    } else {
        feat[tid] = 0.f; feat[128 + tid] = 0.f; feat[256 + tid] = 0.f;
        if (tid == 0) feat[384] = 0.f;
    }
    __syncthreads();
    if (tid < 64) {
        float acc = cb5[tid];
        const float* w = cw5 + (size_t)tid * DCAT;
        for (int k = 0; k < DCAT; k++) acc += w[k] * feat[k];
        h5[((size_t)g * 64 + tid) * 64 + t] = fmaxf(acc, 0.0f);
    }
}

// ---------------- maxpool(2) + conv6 ----------------
__global__ __launch_bounds__(256)
void k_pool_conv6(const float* __restrict__ h5, const float* __restrict__ cw6,
                  const float* __restrict__ cb6, float* __restrict__ h6) {
    int g = blockIdx.x;
    __shared__ float hp[64][33];
    for (int idx = threadIdx.x; idx < 64 * 32; idx += blockDim.x) {
        int i = idx >> 5, u = idx & 31;
        float a = h5[((size_t)g * 64 + i) * 64 + 2 * u];
        float b = h5[((size_t)g * 64 + i) * 64 + 2 * u + 1];
        hp[i][u] = fmaxf(a, b);
    }
    __syncthreads();
    for (int idx = threadIdx.x; idx < 128 * 28; idx += blockDim.x) {
        int o = idx / 28, t = idx % 28;
        float acc = cb6[o];
        const float* w = cw6 + (size_t)o * 320;
#pragma unroll
        for (int i = 0; i < 64; i++) {
#pragma unroll
            for (int j = 0; j < 5; j++) acc += w[i * 5 + j] * hp[i][t + j];
        }
        h6[((size_t)g * 128 + o) * 28 + t] = fmaxf(acc, 0.0f);
    }
}

// ---------------- dense layers ----------------
__global__ __launch_bounds__(256)
void k_dense1(const float* __restrict__ h6, const float* __restrict__ fw1,
              const float* __restrict__ fb1, float* __restrict__ o128) {
    int m = blockIdx.x;
    const int E1 = GG * 128 * 28;  // 39424
    float acc = 0.f;
    const float* w = fw1 + (size_t)m * E1;
    for (int e = threadIdx.x; e < E1; e += 256) acc += h6[e] * w[e];
    __shared__ float s[256];
    s[threadIdx.x] = acc;
    __syncthreads();
    for (int t = 128; t > 0; t >>= 1) {
        if (threadIdx.x < t) s[threadIdx.x] += s[threadIdx.x + t];
        __syncthreads();
    }
    if (threadIdx.x == 0) o128[m] = fmaxf(s[0] + fb1[m], 0.0f);
}
__global__ void k_dense2(const float* __restrict__ o128, const float* __restrict__ fw2,
                         const float* __restrict__ fb2, float* __restrict__ out) {
    int j = threadIdx.x >> 5;
    int lane = threadIdx.x & 31;
    if (j < 10) {
        float acc = 0.f;
        for (int m = lane; m < 128; m += 32) acc += o128[m] * fw2[j * 128 + m];
#pragma unroll
        for (int o = 16; o > 0; o >>= 1) acc += __shfl_down_sync(0xffffffffu, acc, o);
        if (lane == 0) out[j] = acc + fb2[j];
    }
}

// ---------------- launch ----------------
extern "C" void kernel_launch(void* const* d_in, const int* in_sizes, int n_in,
                              void* d_out, int out_size) {
    const float* x   = (const float*)d_in[0];
    const int*   ei  = (const int*)  d_in[1];
    const int*   bat = (const int*)  d_in[2];
    const float* W1  = (const float*)d_in[3];
    const float* b1  = (const float*)d_in[4];
    const float* W2  = (const float*)d_in[5];
    const float* b2  = (const float*)d_in[6];
    const float* W3  = (const float*)d_in[7];
    const float* b3  = (const float*)d_in[8];
    const float* W4  = (const float*)d_in[9];
    const float* b4  = (const float*)d_in[10];
    const float* cw5 = (const float*)d_in[11];
    const float* cb5 = (const float*)d_in[12];
    const float* cw6 = (const float*)d_in[13];
    const float* cb6 = (const float*)d_in[14];
    const float* fw1 = (const float*)d_in[15];
    const float* fb1 = (const float*)d_in[16];
    const float* fw2 = (const float*)d_in[17];
    const float* fb2 = (const float*)d_in[18];

    const int* src = ei;
    const int* dst = ei + NE;

    float *z1, *z2, *z3, *h, *z4, *h4, *deg, *dis, *nrm, *h5, *h6, *o128;
    int* tk;
    cudaGetSymbolAddress((void**)&z1, g_z1);
    cudaGetSymbolAddress((void**)&z2, g_z2);
    cudaGetSymbolAddress((void**)&z3, g_z3);
    cudaGetSymbolAddress((void**)&h,  g_h);
    cudaGetSymbolAddress((void**)&z4, g_z4);
    cudaGetSymbolAddress((void**)&h4, g_h4);
    cudaGetSymbolAddress((void**)&deg, g_deg);
    cudaGetSymbolAddress((void**)&dis, g_dis);
    cudaGetSymbolAddress((void**)&nrm, g_norm);
    cudaGetSymbolAddress((void**)&tk, g_topk);
    cudaGetSymbolAddress((void**)&h5, g_h5);
    cudaGetSymbolAddress((void**)&h6, g_h6);
    cudaGetSymbolAddress((void**)&o128, g_o128);

    cudaFuncSetAttribute(k_topk, cudaFuncAttributeMaxDynamicSharedMemorySize,
                         TOPK_CAP * 4);

    const int TB = 256;
    // degrees and norms
    k_deg_init<<<(NN + TB - 1) / TB, TB>>>(deg, NN);
    k_deg_scatter<<<(NE + TB - 1) / TB, TB>>>(src, dst, deg, NE);
    k_dis<<<(NN + TB - 1) / TB, TB>>>(deg, dis, NN);
    k_norm<<<(NE + TB - 1) / TB, TB>>>(src, dst, dis, nrm, NE);

    const int GEMM_GRID = NN / 128;                 // 3125
    const int SCAT_GRID = (NE * 32) / TB;           // 200000

    // layer 1: A = x (no tanh), K=100
    k_gemm<false><<<GEMM_GRID, TB>>>(x, W1, h, z1, dis, b1, FIN);
    k_scatter<<<SCAT_GRID, TB>>>(h, src, dst, nrm, z1, NE);
    // layer 2
    k_gemm<true><<<GEMM_GRID, TB>>>(z1, W2, h, z2, dis, b2, EMB);
    k_scatter<<<SCAT_GRID, TB>>>(h, src, dst, nrm, z2, NE);
    // layer 3
    k_gemm<true><<<GEMM_GRID, TB>>>(z2, W3, h, z3, dis, b3, EMB);
    k_scatter<<<SCAT_GRID, TB>>>(h, src, dst, nrm, z3, NE);
    // layer 4 (single channel)
    k_gemv4<<<(NN * 32 + TB - 1) / TB, TB>>>(z3, W4, b4, dis, h4, z4, NN);
    k_scatter1<<<(NE + TB - 1) / TB, TB>>>(h4, src, dst, nrm, z4, NE);

    // top-64 per graph (ranks on z4 directly; tanh monotonic)
    k_topk<<<GG, 512, TOPK_CAP * 4>>>(bat, z4, tk, NN);

    // readout
    k_conv5<<<GG * 64, 128>>>(tk, z1, z2, z3, z4, cw5, cb5, h5);
    k_pool_conv6<<<GG, 256>>>(h5, cw6, cb6, h6);
    k_dense1<<<128, 256>>>(h6, fw1, fb1, o128);
    k_dense2<<<1, 320>>>(o128, fw2, fb2, (float*)d_out);
}

// round 4
// speedup vs baseline: 2.0344x; 1.3364x over previous
#include <cuda_runtime.h>
#include <cstdint>
#include <math.h>

#define NN   400000
#define NE   1600000
#define FIN  100
#define EMB  128
#define GG   11
#define SORTK 64
#define DCAT 385   // 3*EMB + 1
#define TOPK_CAP 49152   // floats of dynamic smem cache (192 KB)
#define SCAN_CH 1024
#define SCAN_NB ((NN + SCAN_CH - 1) / SCAN_CH)

// ---------------- device scratch (static, no allocation) ----------------
__device__ float g_z1[51200000];   // pre-tanh layer-1 output
__device__ float g_z2[51200000];
__device__ float g_z3[51200000];
__device__ float g_h [51200000];   // h = act(x_prev) @ W  (current layer)
__device__ float g_z4[NN];
__device__ float g_h4[NN];
__device__ float g_deg[NN];
__device__ float g_dis[NN];
__device__ int   g_rowptr[NN + 1];
__device__ int   g_cursor[NN];
__device__ int   g_csrc[NE];
__device__ float g_csw[NE];
__device__ int   g_bsum[SCAN_NB + 1];
__device__ int   g_topk[GG * SORTK];
__device__ float g_h5[GG * 64 * 64];
__device__ float g_h6[GG * 128 * 28];
__device__ float g_o128[128];

// ---------------- degree ----------------
__global__ void k_deg_init(float* deg, int n) {
    int i = blockIdx.x * blockDim.x + threadIdx.x;
    if (i < n) deg[i] = 1.0f;
}
__global__ void k_deg_scatter(const int* __restrict__ src, const int* __restrict__ dst,
                              float* deg, int e) {
    int i = blockIdx.x * blockDim.x + threadIdx.x;
    if (i < e) {
        int s = src[i], d = dst[i];
        if (s != d) atomicAdd(&deg[d], 1.0f);
    }
}
__global__ void k_dis(const float* __restrict__ deg, float* dis, int n) {
    int i = blockIdx.x * blockDim.x + threadIdx.x;
    if (i < n) dis[i] = rsqrtf(deg[i]);
}

// ---------------- CSR build: exclusive scan of counts = deg-1 ----------------
__global__ __launch_bounds__(256)
void k_scan_part(const float* __restrict__ deg, int* __restrict__ bsum, int n) {
    __shared__ int sh[256];
    int base = blockIdx.x * SCAN_CH;
    int t = threadIdx.x;
    int s = 0;
#pragma unroll
    for (int q = 0; q < 4; q++) {
        int i = base + t * 4 + q;
        if (i < n) s += (int)deg[i] - 1;
    }
    sh[t] = s;
    __syncthreads();
    for (int o = 128; o > 0; o >>= 1) {
        if (t < o) sh[t] += sh[t + o];
        __syncthreads();
    }
    if (t == 0) bsum[blockIdx.x] = sh[0];
}
__global__ void k_scan_mid(int* bsum, int nb, int* rowptr, int n) {
    int run = 0;
    for (int i = 0; i < nb; i++) { int v = bsum[i]; bsum[i] = run; run += v; }
    rowptr[n] = run;
}
__global__ __launch_bounds__(256)
void k_scan_out(const float* __restrict__ deg, const int* __restrict__ bsum,
                int* __restrict__ rowptr, int* __restrict__ cursor, int n) {
    __shared__ int sh[256];
    int base = blockIdx.x * SCAN_CH;
    int t = threadIdx.x;
    int c[4]; int s = 0;
#pragma unroll
    for (int q = 0; q < 4; q++) {
        int i = base + t * 4 + q;
        c[q] = (i < n) ? ((int)deg[i] - 1) : 0;
        s += c[q];
    }
    sh[t] = s;
    __syncthreads();
    for (int o = 1; o < 256; o <<= 1) {
        int u = (t >= o) ? sh[t - o] : 0;
        __syncthreads();
        sh[t] += u;
        __syncthreads();
    }
    int excl = sh[t] - s + bsum[blockIdx.x];
#pragma unroll
    for (int q = 0; q < 4; q++) {
        int i = base + t * 4 + q;
        if (i < n) { rowptr[i] = excl; cursor[i] = excl; excl += c[q]; }
    }
}
__global__ __launch_bounds__(256)
void k_fill(const int* __restrict__ src, const int* __restrict__ dst,
            const float* __restrict__ dis, int* __restrict__ cursor,
            int* __restrict__ csrc, float* __restrict__ csw, int e) {
    int i = blockIdx.x * blockDim.x + threadIdx.x;
    if (i >= e) return;
    int s = src[i], d = dst[i];
    if (s == d) return;
    float w = dis[s] * dis[d];
    int pos = atomicAdd(&cursor[d], 1);
    csrc[pos] = s;
    csw[pos] = w;
}

// ---------------- GEMM: C = act(A) @ B (epilogue moved to gather) ----------------
// BM=128, BN=128, BK=8, 256 threads, 8x8 microtile, double-buffered smem.
template<bool TANH_A>
__global__ __launch_bounds__(256, 2)
void k_gemm(const float* __restrict__ A, const float* __restrict__ B,
            float* __restrict__ C, int K) {
    __shared__ float As[2][8][132];
    __shared__ float Bs[2][8][128];

    const int tid = threadIdx.x;
    const int m0 = (tid >> 4) * 8;
    const int n0 = (tid & 15) * 8;
    const size_t rowBase = (size_t)blockIdx.x * 128;

    const int aRow = tid >> 1;
    const int aCg  = (tid & 1) * 4;
    const int bRow = tid >> 5;
    const int bCol = (tid & 31) * 4;

    const float* Aptr = A + (rowBase + aRow) * (size_t)K;
    const int tiles = (K + 7) / 8;

    float acc[8][8];
#pragma unroll
    for (int i = 0; i < 8; i++)
#pragma unroll
        for (int j = 0; j < 8; j++) acc[i][j] = 0.0f;

    float4 ra, rb;

#define LOAD_T(t, RA, RB) do {                                              \
        int kk = (t) * 8 + aCg;                                             \
        if (kk + 3 < K) {                                                   \
            RA = *reinterpret_cast<const float4*>(Aptr + kk);               \
        } else {                                                            \
            float v0 = (kk + 0 < K) ? Aptr[kk + 0] : 0.0f;                  \
            float v1 = (kk + 1 < K) ? Aptr[kk + 1] : 0.0f;                  \
            float v2 = (kk + 2 < K) ? Aptr[kk + 2] : 0.0f;                  \
            float v3 = (kk + 3 < K) ? Aptr[kk + 3] : 0.0f;                  \
            RA = make_float4(v0, v1, v2, v3);                               \
        }                                                                   \
        int kq = (t) * 8 + bRow;                                            \
        if (kq < K) RB = *reinterpret_cast<const float4*>(B + (size_t)kq * 128 + bCol); \
        else        RB = make_float4(0.f, 0.f, 0.f, 0.f);                   \
    } while (0)

#define STORE_T(buf, RA, RB) do {                                           \
        float v0 = RA.x, v1 = RA.y, v2 = RA.z, v3 = RA.w;                   \
        if (TANH_A) { v0 = tanhf(v0); v1 = tanhf(v1); v2 = tanhf(v2); v3 = tanhf(v3); } \
        As[buf][aCg + 0][aRow] = v0;                                        \
        As[buf][aCg + 1][aRow] = v1;                                        \
        As[buf][aCg + 2][aRow] = v2;                                        \
        As[buf][aCg + 3][aRow] = v3;                                        \
        *reinterpret_cast<float4*>(&Bs[buf][bRow][bCol]) = RB;              \
    } while (0)

    LOAD_T(0, ra, rb);
    STORE_T(0, ra, rb);
    __syncthreads();

    for (int t = 0; t < tiles; t++) {
        const int cur = t & 1;
        const bool more = (t + 1 < tiles);
        float4 na, nb;
        if (more) LOAD_T(t + 1, na, nb);

#pragma unroll
        for (int k = 0; k < 8; k++) {
            float4 a0 = *reinterpret_cast<const float4*>(&As[cur][k][m0]);
            float4 a1 = *reinterpret_cast<const float4*>(&As[cur][k][m0 + 4]);
            float4 b0 = *reinterpret_cast<const float4*>(&Bs[cur][k][n0]);
            float4 b1 = *reinterpret_cast<const float4*>(&Bs[cur][k][n0 + 4]);
            float a[8] = {a0.x, a0.y, a0.z, a0.w, a1.x, a1.y, a1.z, a1.w};
            float b[8] = {b0.x, b0.y, b0.z, b0.w, b1.x, b1.y, b1.z, b1.w};
#pragma unroll
            for (int i = 0; i < 8; i++)
#pragma unroll
                for (int j = 0; j < 8; j++)
                    acc[i][j] += a[i] * b[j];
        }

        if (more) {
            STORE_T(cur ^ 1, na, nb);
            __syncthreads();
        }
    }
#undef LOAD_T
#undef STORE_T

#pragma unroll
    for (int i = 0; i < 8; i++) {
        size_t base = (rowBase + m0 + i) * 128 + n0;
        *reinterpret_cast<float4*>(C + base)     = make_float4(acc[i][0], acc[i][1], acc[i][2], acc[i][3]);
        *reinterpret_cast<float4*>(C + base + 4) = make_float4(acc[i][4], acc[i][5], acc[i][6], acc[i][7]);
    }
}

// ---------------- CSR gather: z[n] = sum_e h[src]*w + h[n]*dis^2 + bias ----------------
// Warp per node. MODE 1 additionally computes h4 = tanh(z) @ W4 and z4 init.
template<int MODE>
__global__ __launch_bounds__(256)
void k_gather(const float* __restrict__ h, const int* __restrict__ rowptr,
              const int* __restrict__ csrc, const float* __restrict__ csw,
              const float* __restrict__ dis, const float* __restrict__ bias,
              float* __restrict__ Z,
              const float* __restrict__ W4, const float* __restrict__ b4,
              float* __restrict__ h4, float* __restrict__ z4) {
    int nid = (blockIdx.x * blockDim.x + threadIdx.x) >> 5;
    if (nid >= NN) return;
    int lane = threadIdx.x & 31;
    int beg = rowptr[nid], end = rowptr[nid + 1];

    float4 acc = make_float4(0.f, 0.f, 0.f, 0.f);
    for (int base = beg; base < end; base += 32) {
        int m = min(32, end - base);
        int s = 0; float w = 0.f;
        if (lane < m) { s = csrc[base + lane]; w = csw[base + lane]; }
        for (int j = 0; j < m; j++) {
            int   ss = __shfl_sync(0xffffffffu, s, j);
            float ww = __shfl_sync(0xffffffffu, w, j);
            float4 v = __ldg(reinterpret_cast<const float4*>(h + (size_t)ss * 128) + lane);
            acc.x += v.x * ww; acc.y += v.y * ww; acc.z += v.z * ww; acc.w += v.w * ww;
        }
    }

    float sn = dis[nid]; sn *= sn;
    float4 hv = *(reinterpret_cast<const float4*>(h + (size_t)nid * 128) + lane);
    float4 bb = reinterpret_cast<const float4*>(bias)[lane];
    float4 z;
    z.x = acc.x + hv.x * sn + bb.x;
    z.y = acc.y + hv.y * sn + bb.y;
    z.z = acc.z + hv.z * sn + bb.z;
    z.w = acc.w + hv.w * sn + bb.w;
    *(reinterpret_cast<float4*>(Z + (size_t)nid * 128) + lane) = z;

    if (MODE == 1) {
        float4 w4 = reinterpret_cast<const float4*>(W4)[lane];
        float t = tanhf(z.x) * w4.x + tanhf(z.y) * w4.y
                + tanhf(z.z) * w4.z + tanhf(z.w) * w4.w;
#pragma unroll
        for (int o = 16; o > 0; o >>= 1) t += __shfl_down_sync(0xffffffffu, t, o);
        if (lane == 0) {
            h4[nid] = t;
            z4[nid] = t * sn + b4[0];
        }
    }
}

// ---------------- layer-4 aggregation: thread per node (no atomics) ----------------
__global__ __launch_bounds__(256)
void k_gather4(const int* __restrict__ rowptr, const int* __restrict__ csrc,
               const float* __restrict__ csw, const float* __restrict__ h4,
               float* __restrict__ z4, int n) {
    int nid = blockIdx.x * blockDim.x + threadIdx.x;
    if (nid >= n) return;
    float a = 0.f;
    int end = rowptr[nid + 1];
    for (int e = rowptr[nid]; e < end; e++)
        a += __ldg(&h4[csrc[e]]) * csw[e];
    z4[nid] += a;
}

// ---------------- top-64 per graph (lexsort-compatible, smem-cached) ----------------
__device__ __forceinline__ int lower_bound_i(const int* b, int n, int v) {
    int lo = 0, hi = n;
    while (lo < hi) { int m = (lo + hi) >> 1; if (b[m] < v) lo = m + 1; else hi = m; }
    return lo;
}
__global__ __launch_bounds__(512)
void k_topk(const int* __restrict__ batch, const float* __restrict__ z4,
            int* __restrict__ topk, int n) {
    int g = blockIdx.x;
    int start = lower_bound_i(batch, n, g);
    int end   = lower_bound_i(batch, n, g + 1);
    int len   = end - start;
    extern __shared__ float sc[];
    const bool cached = (len <= TOPK_CAP);
    if (cached) {
        for (int j = threadIdx.x; j < len; j += blockDim.x) sc[j] = z4[start + j];
    }
    __syncthreads();

    __shared__ unsigned long long warpmax[16];
    __shared__ unsigned long long bestsh;
    const int wid = threadIdx.x >> 5;
    const int lane = threadIdx.x & 31;
    unsigned long long prev = 0xFFFFFFFFFFFFFFFFULL;

    for (int r = 0; r < SORTK; r++) {
        unsigned long long best = 0ULL;
        for (int j = threadIdx.x; j < len; j += blockDim.x) {
            float s = cached ? sc[j] : z4[start + j];
            unsigned u = __float_as_uint(s);
            u = (u & 0x80000000u) ? ~u : (u | 0x80000000u);
            unsigned long long key = ((unsigned long long)u << 32)
                                   | (unsigned)(~(start + j));
            if (key < prev && key > best) best = key;
        }
#pragma unroll
        for (int o = 16; o > 0; o >>= 1) {
            unsigned long long t = __shfl_xor_sync(0xffffffffu, best, o);
            if (t > best) best = t;
        }
        if (lane == 0) warpmax[wid] = best;
        __syncthreads();
        if (wid == 0) {
            unsigned long long v = (lane < 16) ? warpmax[lane] : 0ULL;
#pragma unroll
            for (int o = 8; o > 0; o >>= 1) {
                unsigned long long t = __shfl_xor_sync(0xffffffffu, v, o);
                if (t > v) v = t;
            }
            if (lane == 0) {
                bestsh = v;
                topk[g * SORTK + r] = (v == 0ULL) ? -1
                                     : (int)(~(unsigned)(v & 0xffffffffu));
            }
        }
        __syncthreads();
        prev = bestsh;
        __syncthreads();
    }
}

// ---------------- conv5 ----------------
__global__ __launch_bounds__(128)
void k_conv5(const int* __restrict__ topk,
             const float* __restrict__ z1, const float* __restrict__ z2,
             const float* __restrict__ z3, const float* __restrict__ z4,
             const float* __restrict__ cw5, const float* __restrict__ cb5,
             float* __restrict__ h5) {
    int g = blockIdx.x >> 6;
    int t = blockIdx.x & 63;
    int tid = threadIdx.x;
    __shared__ float feat[DCAT];
    int node = topk[g * SORTK + t];
    if (node >= 0) {
        size_t base = (size_t)node * 128;
        feat[tid]       = tanhf(z1[base + tid]);
        feat[128 + tid] = tanhf(z2[base + tid]);
        feat[256 + tid] = tanhf(z3[base + tid]);
        if (tid == 0) feat[384] = tanhf(z4[node]);
    } else {
        feat[tid] = 0.f; feat[128 + tid] = 0.f; feat[256 + tid] = 0.f;
        if (tid == 0) feat[384] = 0.f;
    }
    __syncthreads();
    if (tid < 64) {
        float acc = cb5[tid];
        const float* w = cw5 + (size_t)tid * DCAT;
        for (int k = 0; k < DCAT; k++) acc += w[k] * feat[k];
        h5[((size_t)g * 64 + tid) * 64 + t] = fmaxf(acc, 0.0f);
    }
}

// ---------------- maxpool(2) + conv6 ----------------
__global__ __launch_bounds__(256)
void k_pool_conv6(const float* __restrict__ h5, const float* __restrict__ cw6,
                  const float* __restrict__ cb6, float* __restrict__ h6) {
    int g = blockIdx.x;
    __shared__ float hp[64][33];
    for (int idx = threadIdx.x; idx < 64 * 32; idx += blockDim.x) {
        int i = idx >> 5, u = idx & 31;
        float a = h5[((size_t)g * 64 + i) * 64 + 2 * u];
        float b = h5[((size_t)g * 64 + i) * 64 + 2 * u + 1];
        hp[i][u] = fmaxf(a, b);
    }
    __syncthreads();
    for (int idx = threadIdx.x; idx < 128 * 28; idx += blockDim.x) {
        int o = idx / 28, t = idx % 28;
        float acc = cb6[o];
        const float* w = cw6 + (size_t)o * 320;
#pragma unroll
        for (int i = 0; i < 64; i++) {
#pragma unroll
            for (int j = 0; j < 5; j++) acc += w[i * 5 + j] * hp[i][t + j];
        }
        h6[((size_t)g * 128 + o) * 28 + t] = fmaxf(acc, 0.0f);
    }
}

// ---------------- dense layers ----------------
__global__ __launch_bounds__(256)
void k_dense1(const float* __restrict__ h6, const float* __restrict__ fw1,
              const float* __restrict__ fb1, float* __restrict__ o128) {
    int m = blockIdx.x;
    const int E1 = GG * 128 * 28;  // 39424
    float acc = 0.f;
    const float* w = fw1 + (size_t)m * E1;
    for (int e = threadIdx.x; e < E1; e += 256) acc += h6[e] * w[e];
    __shared__ float s[256];
    s[threadIdx.x] = acc;
    __syncthreads();
    for (int t = 128; t > 0; t >>= 1) {
        if (threadIdx.x < t) s[threadIdx.x] += s[threadIdx.x + t];
        __syncthreads();
    }
    if (threadIdx.x == 0) o128[m] = fmaxf(s[0] + fb1[m], 0.0f);
}
__global__ void k_dense2(const float* __restrict__ o128, const float* __restrict__ fw2,
                         const float* __restrict__ fb2, float* __restrict__ out) {
    int j = threadIdx.x >> 5;
    int lane = threadIdx.x & 31;
    if (j < 10) {
        float acc = 0.f;
        for (int m = lane; m < 128; m += 32) acc += o128[m] * fw2[j * 128 + m];
#pragma unroll
        for (int o = 16; o > 0; o >>= 1) acc += __shfl_down_sync(0xffffffffu, acc, o);
        if (lane == 0) out[j] = acc + fb2[j];
    }
}

// ---------------- launch ----------------
extern "C" void kernel_launch(void* const* d_in, const int* in_sizes, int n_in,
                              void* d_out, int out_size) {
    const float* x   = (const float*)d_in[0];
    const int*   ei  = (const int*)  d_in[1];
    const int*   bat = (const int*)  d_in[2];
    const float* W1  = (const float*)d_in[3];
    const float* b1  = (const float*)d_in[4];
    const float* W2  = (const float*)d_in[5];
    const float* b2  = (const float*)d_in[6];
    const float* W3  = (const float*)d_in[7];
    const float* b3  = (const float*)d_in[8];
    const float* W4  = (const float*)d_in[9];
    const float* b4  = (const float*)d_in[10];
    const float* cw5 = (const float*)d_in[11];
    const float* cb5 = (const float*)d_in[12];
    const float* cw6 = (const float*)d_in[13];
    const float* cb6 = (const float*)d_in[14];
    const float* fw1 = (const float*)d_in[15];
    const float* fb1 = (const float*)d_in[16];
    const float* fw2 = (const float*)d_in[17];
    const float* fb2 = (const float*)d_in[18];

    const int* src = ei;
    const int* dst = ei + NE;

    float *z1, *z2, *z3, *h, *z4, *h4, *deg, *dis, *csw, *h5, *h6, *o128;
    int *rowptr, *cursor, *csrc, *bsum, *tk;
    cudaGetSymbolAddress((void**)&z1, g_z1);
    cudaGetSymbolAddress((void**)&z2, g_z2);
    cudaGetSymbolAddress((void**)&z3, g_z3);
    cudaGetSymbolAddress((void**)&h,  g_h);
    cudaGetSymbolAddress((void**)&z4, g_z4);
    cudaGetSymbolAddress((void**)&h4, g_h4);
    cudaGetSymbolAddress((void**)&deg, g_deg);
    cudaGetSymbolAddress((void**)&dis, g_dis);
    cudaGetSymbolAddress((void**)&rowptr, g_rowptr);
    cudaGetSymbolAddress((void**)&cursor, g_cursor);
    cudaGetSymbolAddress((void**)&csrc, g_csrc);
    cudaGetSymbolAddress((void**)&csw, g_csw);
    cudaGetSymbolAddress((void**)&bsum, g_bsum);
    cudaGetSymbolAddress((void**)&tk, g_topk);
    cudaGetSymbolAddress((void**)&h5, g_h5);
    cudaGetSymbolAddress((void**)&h6, g_h6);
    cudaGetSymbolAddress((void**)&o128, g_o128);

    cudaFuncSetAttribute(k_topk, cudaFuncAttributeMaxDynamicSharedMemorySize,
                         TOPK_CAP * 4);

    const int TB = 256;
    // degrees
    k_deg_init<<<(NN + TB - 1) / TB, TB>>>(deg, NN);
    k_deg_scatter<<<(NE + TB - 1) / TB, TB>>>(src, dst, deg, NE);
    k_dis<<<(NN + TB - 1) / TB, TB>>>(deg, dis, NN);
    // CSR build
    k_scan_part<<<SCAN_NB, 256>>>(deg, bsum, NN);
    k_scan_mid<<<1, 1>>>(bsum, SCAN_NB, rowptr, NN);
    k_scan_out<<<SCAN_NB, 256>>>(deg, bsum, rowptr, cursor, NN);
    k_fill<<<(NE + TB - 1) / TB, TB>>>(src, dst, dis, cursor, csrc, csw, NE);

    const int GEMM_GRID = NN / 128;                 // 3125
    const int GATH_GRID = (NN * 32) / TB;           // 50000

    // layer 1
    k_gemm<false><<<GEMM_GRID, TB>>>(x, W1, h, FIN);
    k_gather<0><<<GATH_GRID, TB>>>(h, rowptr, csrc, csw, dis, b1, z1,
                                   nullptr, nullptr, nullptr, nullptr);
    // layer 2
    k_gemm<true><<<GEMM_GRID, TB>>>(z1, W2, h, EMB);
    k_gather<0><<<GATH_GRID, TB>>>(h, rowptr, csrc, csw, dis, b2, z2,
                                   nullptr, nullptr, nullptr, nullptr);
    // layer 3 (+ fused layer-4 GEMV)
    k_gemm<true><<<GEMM_GRID, TB>>>(z2, W3, h, EMB);
    k_gather<1><<<GATH_GRID, TB>>>(h, rowptr, csrc, csw, dis, b3, z3,
                                   W4, b4, h4, z4);
    // layer-4 aggregation
    k_gather4<<<(NN + TB - 1) / TB, TB>>>(rowptr, csrc, csw, h4, z4, NN);

    // top-64 per graph
    k_topk<<<GG, 512, TOPK_CAP * 4>>>(bat, z4, tk, NN);

    // readout
    k_conv5<<<GG * 64, 128>>>(tk, z1, z2, z3, z4, cw5, cb5, h5);
    k_pool_conv6<<<GG, 256>>>(h5, cw6, cb6, h6);
    k_dense1<<<128, 256>>>(h6, fw1, fb1, o128);
    k_dense2<<<1, 320>>>(o128, fw2, fb2, (float*)d_out);
}